// round 16
// baseline (speedup 1.0000x reference)
#include <cuda_runtime.h>
#include <math_constants.h>

#define BATCH 32
#define NN 1024
#define MM 1024
#define STRIPS 8
#define RPS 128                    // rows per strip (32 lanes x 4 rows)
#define NCHUNK 33
#define TSTEPS (NCHUNK * 32)       // 1056 wavefront steps per strip
#define WWORDS (TSTEPS / 4)        // 264 packed move words per lane
#define FULLM 0xffffffffu
#define WWIN 73                    // backtrack window word span

// per-lane packed moves: [b][s][w][lane], one byte per step (4 rows x 2 bits)
__device__ unsigned g_mv4[(size_t)BATCH * STRIPS * WWORDS * 32];   // 8.65 MB
__device__ float    g_bnd[(size_t)BATCH * STRIPS * MM];            // strip bottom-row D
__device__ int      g_flag[BATCH * STRIPS * 32];                   // chunk-ready flags
__device__ float    g_loss[BATCH];
__device__ int      g_done;

// scoped acquire/release (no MEMBAR, no STRONG.SYS volatile traffic)
__device__ __forceinline__ int ld_acquire_gpu(const int* p) {
    int v;
    asm volatile("ld.global.acquire.gpu.b32 %0, [%1];" : "=r"(v) : "l"(p) : "memory");
    return v;
}
__device__ __forceinline__ void st_release_gpu(int* p, int v) {
    asm volatile("st.global.release.gpu.b32 [%0], %1;" :: "l"(p), "r"(v) : "memory");
}

// ---------------------------------------------------------------------------
__global__ void dtw_init_kernel()
{
    const int idx = blockIdx.x * blockDim.x + threadIdx.x;
    if (idx < BATCH * STRIPS * 32) g_flag[idx] = 0;
    if (idx == 0) g_done = 0;
}

// ---------------------------------------------------------------------------
// DP: one warp per (batch, strip). Lane r owns rows 4r..4r+3; at step t it
// computes column j = t - r for its 4 rows. One shfl per step; per-lane packed
// move bytes; double-buffered boundary chunks with mid-chunk prefetch.
// ---------------------------------------------------------------------------
#define DP_STEP(TT) do {                                                      \
    const int  t     = c * 32 + (TT);                                         \
    const int  j     = t - r;                                                 \
    const bool valid = (unsigned)j < (unsigned)MM;                            \
    const float sh  = __shfl_up_sync(FULLM, left3, 1);                        \
    const float up0 = (r == 0) ? bl[(TT)] : sh;                               \
    const float e0 = fminf(dg0,   left0);                                     \
    const float e1 = fminf(left0, left1);                                     \
    const float e2 = fminf(left1, left2);                                     \
    const float e3 = fminf(left2, left3);                                     \
    const float2 tc = s_tp[j + 32];                                           \
    float dx, dy;                                                             \
    dx = px0 - tc.x; dy = py0 - tc.y; float c0 = sqrtf(dx*dx + dy*dy);        \
    dx = px1 - tc.x; dy = py1 - tc.y; float c1 = sqrtf(dx*dx + dy*dy);        \
    dx = px2 - tc.x; dy = py2 - tc.y; float c2 = sqrtf(dx*dx + dy*dy);        \
    dx = px3 - tc.x; dy = py3 - tc.y; float c3 = sqrtf(dx*dx + dy*dy);        \
    if (!valid) { c0 = INF; c1 = INF; c2 = INF; c3 = INF; }                   \
    float cur0 = c0 + fminf(up0,  e0);                                        \
    if ((TT) == 0) { if (seed00 && c == 0) cur0 = c0; }  /* D[0][0] seed */   \
    const float cur1 = c1 + fminf(cur0, e1);                                  \
    const float cur2 = c2 + fminf(cur1, e2);                                  \
    const float cur3 = c3 + fminf(cur2, e3);                                  \
    unsigned m0 = 0, m1 = 0, m2 = 0, m3 = 0;                                  \
    { float bv = dg0;   if (up0  < bv) { m0 = 1; bv = up0;  } if (left0 < bv) m0 = 2; } \
    { float bv = left0; if (cur0 < bv) { m1 = 1; bv = cur0; } if (left1 < bv) m1 = 2; } \
    { float bv = left1; if (cur1 < bv) { m2 = 1; bv = cur1; } if (left2 < bv) m2 = 2; } \
    { float bv = left2; if (cur2 < bv) { m3 = 1; bv = cur2; } if (left3 < bv) m3 = 2; } \
    mreg |= (m0 | (m1 << 2) | (m2 << 4) | (m3 << 6)) << (((TT) & 3) * 8);     \
    if ((((TT)) & 3) == 3) { mv[(size_t)(t >> 2) * 32] = mreg; mreg = 0; }    \
    if (r == 31 && s < STRIPS - 1 && valid) bnd_wr[j] = cur3;                 \
    dg0 = up0; left0 = cur0; left1 = cur1; left2 = cur2; left3 = cur3;        \
} while (0)

__global__ __launch_bounds__(32, 1)     // single-warp CTA, ~2/SM: give ptxas full regs
void dtw_dp_kernel(const float* __restrict__ preds,
                   const float* __restrict__ targs)
{
    const int bid = blockIdx.x;               // s * BATCH + b  (producers first)
    const int b   = bid & (BATCH - 1);
    const int s   = bid / BATCH;
    const int r   = threadIdx.x;
    const float INF = CUDART_INF_F;
    const bool seed00 = (s == 0) && (r == 0);

    __shared__ float2 s_tp[1088];             // targ coords, padded +-32
    __shared__ float  s_bnd[2][32];           // double-buffered boundary chunks

    const float4* tb4 = (const float4*)(targs + (size_t)b * MM * 4);
    #pragma unroll 4
    for (int i = r; i < MM; i += 32) {
        const float4 v = tb4[i];
        s_tp[i + 32] = make_float2(v.x, v.y);
    }
    s_tp[r] = make_float2(0.f, 0.f);
    s_tp[1056 + r] = make_float2(0.f, 0.f);
    s_bnd[0][r] = INF;
    s_bnd[1][r] = INF;
    __syncwarp();

    const float4* pb4 = (const float4*)(preds + (size_t)b * NN * 4);
    const int row0 = s * RPS + 4 * r;
    const float4 a0 = pb4[row0 + 0], a1 = pb4[row0 + 1];
    const float4 a2 = pb4[row0 + 2], a3 = pb4[row0 + 3];
    const float px0 = a0.x, py0 = a0.y, px1 = a1.x, py1 = a1.y;
    const float px2 = a2.x, py2 = a2.y, px3 = a3.x, py3 = a3.y;

    float*       bnd_wr  = g_bnd  + ((size_t)b * STRIPS + s) * MM;
    const float* bnd_rd  = g_bnd  + ((size_t)b * STRIPS + s - 1) * MM;
    int*         flag_rd = g_flag + (b * STRIPS + s - 1) * 32;
    int*         flag_wr = g_flag + (b * STRIPS + s) * 32;
    unsigned*    mv      = g_mv4  + (size_t)(b * STRIPS + s) * WWORDS * 32 + r;

    float left0 = INF, left1 = INF, left2 = INF, left3 = INF, dg0 = INF;

    if (s > 0) {                              // blocking fetch of boundary chunk 0
        if (r == 0) { while (ld_acquire_gpu(&flag_rd[0]) == 0) { } }
        __syncwarp();
        s_bnd[0][r] = bnd_rd[r];
        __syncwarp();
    }

    unsigned mreg = 0;
    #pragma unroll 1
    for (int c = 0; c < NCHUNK; ++c) {
        const int cb = c & 1;
        const float* bl = s_bnd[cb];

        #pragma unroll 1
        for (int u = 0; u < 4; ++u) {         // first half: steps 0..15
            #pragma unroll
            for (int v = 0; v < 4; ++v) DP_STEP(u * 4 + v);
        }

        if (s > 0 && c < 31) {                // mid-chunk prefetch of chunk c+1
            if (r == 0) { while (ld_acquire_gpu(&flag_rd[c + 1]) == 0) { } }
            __syncwarp();
            s_bnd[cb ^ 1][r] = bnd_rd[(c + 1) * 32 + r];
            __syncwarp();
        }

        #pragma unroll 1
        for (int u = 4; u < 8; ++u) {         // second half: steps 16..31
            #pragma unroll
            for (int v = 0; v < 4; ++v) DP_STEP(u * 4 + v);
        }

        if (s < STRIPS - 1 && c >= 1 && r == 31) {
            st_release_gpu(&flag_wr[c - 1], 1);   // release bnd columns of chunk c-1
        }
    }
}

// ---------------------------------------------------------------------------
// Backtrack (windowed, moves staged to shared) + parallel loss + deterministic
// cross-batch sum via last-block ticket. One CTA per batch.
// ---------------------------------------------------------------------------
__global__ __launch_bounds__(1024, 1)
void dtw_bt_kernel(const float* __restrict__ preds,
                   const float* __restrict__ targs,
                   const float* __restrict__ subcoef,
                   float* __restrict__ out)
{
    __shared__ unsigned s_win[3 * WWIN * 32];   // 28 KB
    __shared__ int      s_path[2048];
    __shared__ float    s_red[32];
    __shared__ int      s_ctl[4];               // i, j, len, done

    const int b    = blockIdx.x;
    const int tid  = threadIdx.x;
    const int warp = tid >> 5;
    const int lane = tid & 31;

    if (tid == 0) { s_ctl[0] = NN - 1; s_ctl[1] = MM - 1; s_ctl[2] = 0; s_ctl[3] = 0; }
    __syncthreads();

    int guard = 0;                              // >=255 progress per window => <=10 needed
    #pragma unroll 1
    while (s_ctl[3] == 0 && guard++ < 40) {
        const int i0  = s_ctl[0], j0 = s_ctl[1];
        const int slo = max(0, i0 - 255) >> 7;
        const int shi = i0 >> 7;
        const int nst = shi - slo + 1;          // <= 3
        const int jlo = max(0, j0 - 255);
        const int wlo = jlo >> 2;
        const int whi = (j0 + 31) >> 2;
        const int nwd = whi - wlo + 1;          // <= 73

        // stage window (contiguous per strip: consecutive idx -> consecutive addr)
        const int tot = nst * nwd * 32;
        for (int idx = tid; idx < tot; idx += 1024) {
            const int ss  = idx / (nwd * 32);
            const int rem = idx - ss * (nwd * 32);
            s_win[ss * (WWIN * 32) + rem] =
                g_mv4[((size_t)(b * STRIPS + slo + ss) * WWORDS + wlo) * 32 + rem];
        }
        __syncthreads();

        if (tid == 0) {
            int i = i0, j = j0, len = s_ctl[2], done = 0;
            const int ilim = slo << 7;
            #pragma unroll 1
            while (i >= ilim && j >= jlo && len < 2048) {
                s_path[len++] = (i << 11) | j;
                if ((i | j) == 0) { done = 1; break; }
                const int rr = (i >> 2) & 31;
                const int t  = j + rr;
                const unsigned w =
                    s_win[(((i >> 7) - slo) * WWIN + ((t >> 2) - wlo)) * 32 + rr];
                const int m = (w >> (((t & 3) << 3) + ((i & 3) << 1))) & 3;
                i -= (m == 2) ? 0 : 1;
                j -= (m == 1) ? 0 : 1;
            }
            s_ctl[0] = i; s_ctl[1] = j; s_ctl[2] = len; s_ctl[3] = done;
        }
        __syncthreads();
    }

    // parallel loss over recorded path (coords from global; L1/L2-hit, MLP-rich)
    const int   len = s_ctl[2];
    const float sc0 = subcoef[0];
    const float sc1 = subcoef[1];
    const float2* pb2 = (const float2*)(preds + (size_t)b * NN * 4);
    const float2* tb2 = (const float2*)(targs + (size_t)b * MM * 4);

    float acc = 0.0f;
    for (int e = tid; e < len; e += 1024) {
        const int p  = s_path[e];
        const int pi = p >> 11;
        const int pj = p & 2047;
        const float2 pp = pb2[2 * pi];
        const float2 tt = tb2[2 * pj];
        acc += fabsf(pp.x - tt.x) * sc0 + fabsf(pp.y - tt.y) * sc1;
    }
    #pragma unroll
    for (int o = 16; o > 0; o >>= 1) acc += __shfl_down_sync(FULLM, acc, o);
    if (lane == 0) s_red[warp] = acc;
    __syncthreads();
    if (warp == 0) {
        float v = s_red[lane];
        #pragma unroll
        for (int o = 16; o > 0; o >>= 1) v += __shfl_down_sync(FULLM, v, o);
        if (lane == 0) {
            g_loss[b] = v;
            __threadfence();
            const int ticket = atomicAdd(&g_done, 1);
            if (ticket == BATCH - 1) {          // last block: fixed-order sum
                __threadfence();
                float su = 0.0f;
                #pragma unroll
                for (int k = 0; k < BATCH; ++k) su += g_loss[k];
                out[0] = su;
            }
        }
    }
}

extern "C" void kernel_launch(void* const* d_in, const int* in_sizes, int n_in,
                              void* d_out, int out_size)
{
    const float* preds   = (const float*)d_in[0];
    const float* targs   = (const float*)d_in[1];
    const float* subcoef = (const float*)d_in[2];
    float* out = (float*)d_out;

    dtw_init_kernel<<<8, 1024>>>();
    dtw_dp_kernel<<<BATCH * STRIPS, 32>>>(preds, targs);
    dtw_bt_kernel<<<BATCH, 1024>>>(preds, targs, subcoef, out);
}

// round 17
// speedup vs baseline: 2.0579x; 2.0579x over previous
#include <cuda_runtime.h>
#include <math_constants.h>

#define BATCH 32
#define NN 1024
#define MM 1024
#define STRIPS 16
#define RPS 64                     // rows per strip (32 lanes x 2 rows)
#define NCHUNK 33
#define TSTEPS (NCHUNK * 32)       // 1056 wavefront steps per strip
#define WORDS8 (TSTEPS / 8)        // 132 packed move words per lane (8 steps/word)
#define FULLM 0xffffffffu
#define WWIN 37                    // backtrack window word span

// per-lane packed moves: [b][s][w][lane]; nibble per step = 2 rows x 2 bits
__device__ unsigned g_mv8[(size_t)BATCH * STRIPS * WORDS8 * 32];   // 8.65 MB
__device__ float    g_bnd[(size_t)BATCH * STRIPS * MM];            // strip bottom-row D
__device__ int      g_flag[BATCH * STRIPS * 32];                   // chunk-ready flags
__device__ float    g_loss[BATCH];
__device__ int      g_done;

__device__ __forceinline__ float sqrt_approx(float x) {
    float y;
    asm("sqrt.approx.f32 %0, %1;" : "=f"(y) : "f"(x));
    return y;
}

// ---------------------------------------------------------------------------
__global__ void dtw_init_kernel()
{
    const int idx = blockIdx.x * blockDim.x + threadIdx.x;
    if (idx < BATCH * STRIPS * 32) g_flag[idx] = 0;
    if (idx == 0) g_done = 0;
}

// ---------------------------------------------------------------------------
// DP: one warp per (batch, strip). Lane r owns rows 2r, 2r+1; at step t it
// computes column j = t - r for both rows. One shfl + two MUFU.SQRT per step;
// per-lane nibble-packed moves; double-buffered boundary chunks w/ prefetch.
// ---------------------------------------------------------------------------
#define DP_STEP(TT) do {                                                      \
    const int  t     = c * 32 + (TT);                                         \
    const int  j     = t - r;                                                 \
    const bool valid = (unsigned)j < (unsigned)MM;                            \
    const float sh  = __shfl_up_sync(FULLM, left1, 1);                        \
    const float up0 = (r == 0) ? bl[(TT)] : sh;                               \
    const float e0 = fminf(dg0,   left0);                                     \
    const float e1 = fminf(left0, left1);                                     \
    const float2 tc = s_tp[j + 32];                                           \
    float dx, dy;                                                             \
    dx = px0 - tc.x; dy = py0 - tc.y; float c0 = sqrt_approx(dx*dx + dy*dy);  \
    dx = px1 - tc.x; dy = py1 - tc.y; float c1 = sqrt_approx(dx*dx + dy*dy);  \
    if (!valid) { c0 = INF; c1 = INF; }                                       \
    float cur0 = c0 + fminf(up0, e0);                                         \
    if ((TT) == 0) { if (seed00 && c == 0) cur0 = c0; }  /* D[0][0] seed */   \
    const float cur1 = c1 + fminf(cur0, e1);                                  \
    unsigned m0 = 0, m1 = 0;                                                  \
    { float bv = dg0;   if (up0  < bv) { m0 = 1; bv = up0;  } if (left0 < bv) m0 = 2; } \
    { float bv = left0; if (cur0 < bv) { m1 = 1; bv = cur0; } if (left1 < bv) m1 = 2; } \
    mreg |= (m0 | (m1 << 2)) << (((TT) & 7) * 4);                             \
    if (((TT) & 7) == 7) { mv[(size_t)(t >> 3) * 32] = mreg; mreg = 0; }      \
    if (r == 31 && s < STRIPS - 1 && valid) bnd_wr[j] = cur1;                 \
    dg0 = up0; left0 = cur0; left1 = cur1;                                    \
} while (0)

__global__ __launch_bounds__(32, 32)
void dtw_dp_kernel(const float* __restrict__ preds,
                   const float* __restrict__ targs)
{
    const int bid = blockIdx.x;               // s * BATCH + b  (producers first)
    const int b   = bid & (BATCH - 1);
    const int s   = bid / BATCH;
    const int r   = threadIdx.x;
    const float INF = CUDART_INF_F;
    const bool seed00 = (s == 0) && (r == 0);

    __shared__ float2 s_tp[1088];             // targ coords, padded +-32
    __shared__ float  s_bnd[2][32];           // double-buffered boundary chunks

    const float4* tb4 = (const float4*)(targs + (size_t)b * MM * 4);
    #pragma unroll 4
    for (int i = r; i < MM; i += 32) {
        const float4 v = tb4[i];
        s_tp[i + 32] = make_float2(v.x, v.y);
    }
    s_tp[r] = make_float2(0.f, 0.f);
    s_tp[1056 + r] = make_float2(0.f, 0.f);
    s_bnd[0][r] = INF;
    s_bnd[1][r] = INF;
    __syncwarp();

    const float4* pb4 = (const float4*)(preds + (size_t)b * NN * 4);
    const int row0 = s * RPS + 2 * r;
    const float4 a0 = pb4[row0 + 0], a1 = pb4[row0 + 1];
    const float px0 = a0.x, py0 = a0.y, px1 = a1.x, py1 = a1.y;

    float*        bnd_wr  = g_bnd  + ((size_t)b * STRIPS + s) * MM;
    const float*  bnd_rd  = g_bnd  + ((size_t)b * STRIPS + s - 1) * MM;
    volatile int* flag_rd = g_flag + (b * STRIPS + s - 1) * 32;
    int*          flag_wr = g_flag + (b * STRIPS + s) * 32;
    unsigned*     mv      = g_mv8  + (size_t)(b * STRIPS + s) * WORDS8 * 32 + r;

    float left0 = INF, left1 = INF, dg0 = INF;

    if (s > 0) {                              // blocking fetch of boundary chunk 0
        if (r == 0) { while (flag_rd[0] == 0) { } }
        __syncwarp();
        __threadfence();
        s_bnd[0][r] = bnd_rd[r];
        __syncwarp();
    }

    unsigned mreg = 0;
    #pragma unroll 1
    for (int c = 0; c < NCHUNK; ++c) {
        const int cb = c & 1;
        const float* bl = s_bnd[cb];

        #pragma unroll 1
        for (int u = 0; u < 4; ++u) {         // first half: steps 0..15
            #pragma unroll
            for (int v = 0; v < 4; ++v) DP_STEP(u * 4 + v);
        }

        if (s > 0 && c < 31) {                // mid-chunk prefetch of chunk c+1
            if (r == 0) { while (flag_rd[c + 1] == 0) { } }
            __syncwarp();
            __threadfence();
            s_bnd[cb ^ 1][r] = bnd_rd[(c + 1) * 32 + r];
            __syncwarp();
        }

        #pragma unroll 1
        for (int u = 4; u < 8; ++u) {         // second half: steps 16..31
            #pragma unroll
            for (int v = 0; v < 4; ++v) DP_STEP(u * 4 + v);
        }

        if (s < STRIPS - 1 && c >= 1 && r == 31) {
            __threadfence();                  // release bnd columns of chunk c-1
            *(volatile int*)&flag_wr[c - 1] = 1;
        }
    }
}

// ---------------------------------------------------------------------------
// Backtrack (windowed, moves staged to shared) + parallel loss + deterministic
// cross-batch sum via last-block ticket. One CTA per batch.
// ---------------------------------------------------------------------------
__global__ __launch_bounds__(1024, 1)
void dtw_bt_kernel(const float* __restrict__ preds,
                   const float* __restrict__ targs,
                   const float* __restrict__ subcoef,
                   float* __restrict__ out)
{
    __shared__ unsigned s_win[5 * WWIN * 32];   // 23.7 KB
    __shared__ int      s_path[2048];
    __shared__ float    s_red[32];
    __shared__ int      s_ctl[4];               // i, j, len, done

    const int b    = blockIdx.x;
    const int tid  = threadIdx.x;
    const int warp = tid >> 5;
    const int lane = tid & 31;

    if (tid == 0) { s_ctl[0] = NN - 1; s_ctl[1] = MM - 1; s_ctl[2] = 0; s_ctl[3] = 0; }
    __syncthreads();

    int guard = 0;                              // >=255 progress per window => <=9 needed
    #pragma unroll 1
    while (s_ctl[3] == 0 && guard++ < 40) {
        const int i0  = s_ctl[0], j0 = s_ctl[1];
        const int slo = max(0, i0 - 255) >> 6;
        const int shi = i0 >> 6;
        const int nst = shi - slo + 1;          // <= 5
        const int jlo = max(0, j0 - 255);
        const int wlo = jlo >> 3;
        const int whi = (j0 + 31) >> 3;
        const int nwd = whi - wlo + 1;          // <= 37

        // stage window (contiguous per strip: consecutive idx -> consecutive addr)
        const int tot = nst * nwd * 32;
        for (int idx = tid; idx < tot; idx += 1024) {
            const int ss  = idx / (nwd * 32);
            const int rem = idx - ss * (nwd * 32);
            s_win[ss * (WWIN * 32) + rem] =
                g_mv8[((size_t)(b * STRIPS + slo + ss) * WORDS8 + wlo) * 32 + rem];
        }
        __syncthreads();

        if (tid == 0) {
            int i = i0, j = j0, len = s_ctl[2], done = 0;
            const int ilim = slo << 6;
            #pragma unroll 1
            while (i >= ilim && j >= jlo && len < 2048) {
                s_path[len++] = (i << 11) | j;
                if ((i | j) == 0) { done = 1; break; }
                const int li = i & 63;
                const int rr = li >> 1;
                const int q  = li & 1;
                const int t  = j + rr;
                const unsigned w =
                    s_win[(((i >> 6) - slo) * WWIN + ((t >> 3) - wlo)) * 32 + rr];
                const int m = (w >> (((t & 7) << 2) + (q << 1))) & 3;
                i -= (m == 2) ? 0 : 1;
                j -= (m == 1) ? 0 : 1;
            }
            s_ctl[0] = i; s_ctl[1] = j; s_ctl[2] = len; s_ctl[3] = done;
        }
        __syncthreads();
    }

    // parallel loss over recorded path (coords from global; L1/L2-hit, MLP-rich)
    const int   len = s_ctl[2];
    const float sc0 = subcoef[0];
    const float sc1 = subcoef[1];
    const float2* pb2 = (const float2*)(preds + (size_t)b * NN * 4);
    const float2* tb2 = (const float2*)(targs + (size_t)b * MM * 4);

    float acc = 0.0f;
    for (int e = tid; e < len; e += 1024) {
        const int p  = s_path[e];
        const int pi = p >> 11;
        const int pj = p & 2047;
        const float2 pp = pb2[2 * pi];
        const float2 tt = tb2[2 * pj];
        acc += fabsf(pp.x - tt.x) * sc0 + fabsf(pp.y - tt.y) * sc1;
    }
    #pragma unroll
    for (int o = 16; o > 0; o >>= 1) acc += __shfl_down_sync(FULLM, acc, o);
    if (lane == 0) s_red[warp] = acc;
    __syncthreads();
    if (warp == 0) {
        float v = s_red[lane];
        #pragma unroll
        for (int o = 16; o > 0; o >>= 1) v += __shfl_down_sync(FULLM, v, o);
        if (lane == 0) {
            g_loss[b] = v;
            __threadfence();
            const int ticket = atomicAdd(&g_done, 1);
            if (ticket == BATCH - 1) {          // last block: fixed-order sum
                __threadfence();
                float su = 0.0f;
                #pragma unroll
                for (int k = 0; k < BATCH; ++k) su += g_loss[k];
                out[0] = su;
            }
        }
    }
}

extern "C" void kernel_launch(void* const* d_in, const int* in_sizes, int n_in,
                              void* d_out, int out_size)
{
    const float* preds   = (const float*)d_in[0];
    const float* targs   = (const float*)d_in[1];
    const float* subcoef = (const float*)d_in[2];
    float* out = (float*)d_out;

    dtw_init_kernel<<<16, 1024>>>();
    dtw_dp_kernel<<<BATCH * STRIPS, 32>>>(preds, targs);
    dtw_bt_kernel<<<BATCH, 1024>>>(preds, targs, subcoef, out);
}